// round 16
// baseline (speedup 1.0000x reference)
#include <cuda_runtime.h>

// ---------------------------------------------------------------------------
// CrossAttentionBlock with kv_len == 1:
//   softmax over a single key == 1.0 exactly, so attention output == v
//   broadcast over all 4096 query positions. q, k, GroupNorm, qw, kw are
//   dead code. The whole block reduces to:
//     a    = LayerNorm(act[b])                      (256)
//     v    = a @ vw + vb                            (256x256 matvec)
//     y    = v @ ow + ob                            (256x256 matvec)
//     out[b,c,h,w] = img[b,c,h,w] + y[b,c]          (broadcast add, 268MB)
// ---------------------------------------------------------------------------

#define B_  32
#define C_  256
#define HW_ 4096   // 64*64

__device__ float g_y[B_ * C_];   // per-(batch,channel) additive term

// ---- Stage 1: one CTA per batch, 256 threads (thread t owns channel t) ----
__global__ void __launch_bounds__(C_) compute_y_kernel(
    const float* __restrict__ act,
    const float* __restrict__ ln_w, const float* __restrict__ ln_b,
    const float* __restrict__ vw,   const float* __restrict__ vb,
    const float* __restrict__ ow,   const float* __restrict__ ob)
{
    __shared__ float s_a[C_];
    __shared__ float s_v[C_];
    __shared__ float s_red[8];

    const int b = blockIdx.x;
    const int t = threadIdx.x;

    const float x = act[b * C_ + t];

    // --- mean ---
    float s = x;
    #pragma unroll
    for (int o = 16; o; o >>= 1) s += __shfl_xor_sync(0xffffffffu, s, o);
    if ((t & 31) == 0) s_red[t >> 5] = s;
    __syncthreads();
    float tot = 0.f;
    #pragma unroll
    for (int i = 0; i < 8; i++) tot += s_red[i];
    const float mu = tot * (1.0f / 256.0f);
    __syncthreads();   // s_red reuse

    // --- variance ---
    const float dx = x - mu;
    s = dx * dx;
    #pragma unroll
    for (int o = 16; o; o >>= 1) s += __shfl_xor_sync(0xffffffffu, s, o);
    if ((t & 31) == 0) s_red[t >> 5] = s;
    __syncthreads();
    tot = 0.f;
    #pragma unroll
    for (int i = 0; i < 8; i++) tot += s_red[i];
    const float var = tot * (1.0f / 256.0f);

    // --- LayerNorm ---
    const float a = dx * rsqrtf(var + 1e-5f) * ln_w[t] + ln_b[t];
    s_a[t] = a;
    __syncthreads();

    // --- v = a @ vw + vb  (thread t computes column t; coalesced vw reads) ---
    float v0 = 0.f, v1 = 0.f, v2 = 0.f, v3 = 0.f;
    #pragma unroll 4
    for (int i = 0; i < C_; i += 4) {
        v0 = fmaf(s_a[i + 0], vw[(i + 0) * C_ + t], v0);
        v1 = fmaf(s_a[i + 1], vw[(i + 1) * C_ + t], v1);
        v2 = fmaf(s_a[i + 2], vw[(i + 2) * C_ + t], v2);
        v3 = fmaf(s_a[i + 3], vw[(i + 3) * C_ + t], v3);
    }
    const float v = vb[t] + ((v0 + v1) + (v2 + v3));
    s_v[t] = v;
    __syncthreads();

    // --- y = v @ ow + ob ---
    float y0 = 0.f, y1 = 0.f, y2 = 0.f, y3 = 0.f;
    #pragma unroll 4
    for (int i = 0; i < C_; i += 4) {
        y0 = fmaf(s_v[i + 0], ow[(i + 0) * C_ + t], y0);
        y1 = fmaf(s_v[i + 1], ow[(i + 1) * C_ + t], y1);
        y2 = fmaf(s_v[i + 2], ow[(i + 2) * C_ + t], y2);
        y3 = fmaf(s_v[i + 3], ow[(i + 3) * C_ + t], y3);
    }
    g_y[b * C_ + t] = ob[t] + ((y0 + y1) + (y2 + y3));
}

// ---- Stage 2: one CTA per (b,c) channel; 4096 floats = 1024 float4 --------
__global__ void __launch_bounds__(256) add_bcast_kernel(
    const float* __restrict__ img, float* __restrict__ out)
{
    const int bc = blockIdx.x;                   // 0 .. 8191
    const float yv = g_y[bc];                    // uniform per block (L1/L2 hit)

    const float4* __restrict__ in4  = reinterpret_cast<const float4*>(img) +
                                      (size_t)bc * (HW_ / 4);
    float4* __restrict__ out4 = reinterpret_cast<float4*>(out) +
                                (size_t)bc * (HW_ / 4);
    const int t = threadIdx.x;
    #pragma unroll
    for (int i = 0; i < 4; i++) {
        float4 p = in4[t + i * 256];
        p.x += yv; p.y += yv; p.z += yv; p.w += yv;
        out4[t + i * 256] = p;
    }
}

extern "C" void kernel_launch(void* const* d_in, const int* in_sizes, int n_in,
                              void* d_out, int out_size)
{
    // metadata order: img, act, gn_w, gn_b, ln_w, ln_b, qw, qb, kw, kb,
    //                 vw, vb, ow, ob
    const float* img  = (const float*)d_in[0];
    const float* act  = (const float*)d_in[1];
    const float* ln_w = (const float*)d_in[4];
    const float* ln_b = (const float*)d_in[5];
    const float* vw   = (const float*)d_in[10];
    const float* vb   = (const float*)d_in[11];
    const float* ow   = (const float*)d_in[12];
    const float* ob   = (const float*)d_in[13];

    compute_y_kernel<<<B_, C_>>>(act, ln_w, ln_b, vw, vb, ow, ob);
    add_bcast_kernel<<<B_ * C_, 256>>>(img, (float*)d_out);
}

// round 17
// speedup vs baseline: 1.1047x; 1.1047x over previous
#include <cuda_runtime.h>

// ---------------------------------------------------------------------------
// CrossAttentionBlock with kv_len == 1 collapses to:
//   a = LayerNorm(act[b]); v = a@vw+vb; y = v@ow+ob
//   out[b,c,h,w] = img[b,c,h,w] + y[b,c]
//
// Single fused kernel:
//   blocks 0..31      : producers — compute y[b,:] for batch b, bump g_ready
//   blocks 32..8223   : consumers — one (b,c) channel each. Issue all img
//                       loads FIRST (registers), spin-wait on g_ready (only
//                       thread 0, with nanosleep backoff), then add + store.
// The 134MB img read stream overlaps the tiny y computation; only the
// stores serialize behind it. Counters self-reset (last CTA), so the kernel
// is deterministic across graph replays.
// ---------------------------------------------------------------------------

#define B_   32
#define C_   256
#define HW_  4096                 // 64*64
#define NCONS (B_ * C_)           // 8192 consumer CTAs
#define GRID_ (NCONS + B_)        // 8224 total

__device__ float g_y[B_ * C_];
__device__ int   g_ready;         // producers done count (0..32)
__device__ int   g_done;          // CTA completion count (for reset)

__global__ void __launch_bounds__(256) fused_xattn_kernel(
    const float* __restrict__ img,
    const float* __restrict__ act,
    const float* __restrict__ ln_w, const float* __restrict__ ln_b,
    const float* __restrict__ vw,   const float* __restrict__ vb,
    const float* __restrict__ ow,   const float* __restrict__ ob,
    float* __restrict__ out)
{
    const int t   = threadIdx.x;
    const int bid = blockIdx.x;

    if (bid < B_) {
        // ================= producer: y[b, :] =================
        __shared__ float s_a[C_];
        __shared__ float s_v[C_];
        __shared__ float s_red[8];
        const int b = bid;

        const float x = act[b * C_ + t];

        // mean
        float s = x;
        #pragma unroll
        for (int o = 16; o; o >>= 1) s += __shfl_xor_sync(0xffffffffu, s, o);
        if ((t & 31) == 0) s_red[t >> 5] = s;
        __syncthreads();
        float tot = 0.f;
        #pragma unroll
        for (int i = 0; i < 8; i++) tot += s_red[i];
        const float mu = tot * (1.0f / 256.0f);
        __syncthreads();

        // variance
        const float dx = x - mu;
        s = dx * dx;
        #pragma unroll
        for (int o = 16; o; o >>= 1) s += __shfl_xor_sync(0xffffffffu, s, o);
        if ((t & 31) == 0) s_red[t >> 5] = s;
        __syncthreads();
        tot = 0.f;
        #pragma unroll
        for (int i = 0; i < 8; i++) tot += s_red[i];
        const float var = tot * (1.0f / 256.0f);

        // LayerNorm
        const float a = dx * rsqrtf(var + 1e-5f) * ln_w[t] + ln_b[t];
        s_a[t] = a;
        __syncthreads();

        // v = a @ vw + vb   (8 accumulators, full unroll -> high MLP)
        {
            float acc[8] = {0.f,0.f,0.f,0.f,0.f,0.f,0.f,0.f};
            #pragma unroll
            for (int i = 0; i < C_; i += 8) {
                #pragma unroll
                for (int j = 0; j < 8; j++)
                    acc[j] = fmaf(s_a[i + j], vw[(i + j) * C_ + t], acc[j]);
            }
            float v = vb[t];
            v += ((acc[0] + acc[1]) + (acc[2] + acc[3]))
               + ((acc[4] + acc[5]) + (acc[6] + acc[7]));
            s_v[t] = v;
        }
        __syncthreads();

        // y = v @ ow + ob
        {
            float acc[8] = {0.f,0.f,0.f,0.f,0.f,0.f,0.f,0.f};
            #pragma unroll
            for (int i = 0; i < C_; i += 8) {
                #pragma unroll
                for (int j = 0; j < 8; j++)
                    acc[j] = fmaf(s_v[i + j], ow[(i + j) * C_ + t], acc[j]);
            }
            float y = ob[t];
            y += ((acc[0] + acc[1]) + (acc[2] + acc[3]))
               + ((acc[4] + acc[5]) + (acc[6] + acc[7]));
            g_y[b * C_ + t] = y;
        }
        __syncthreads();            // all 256 y values written
        if (t == 0) {
            __threadfence();        // release g_y before bumping counter
            atomicAdd(&g_ready, 1);
        }
    } else {
        // ================= consumer: one (b,c) channel =================
        const int bc = bid - B_;
        const float4* __restrict__ in4 =
            reinterpret_cast<const float4*>(img) + (size_t)bc * (HW_ / 4);
        float4* __restrict__ out4 =
            reinterpret_cast<float4*>(out) + (size_t)bc * (HW_ / 4);

        // Issue ALL loads before waiting — overlaps DRAM read with y compute.
        float4 p0 = __ldcs(&in4[t]);
        float4 p1 = __ldcs(&in4[t + 256]);
        float4 p2 = __ldcs(&in4[t + 512]);
        float4 p3 = __ldcs(&in4[t + 768]);

        __shared__ float s_y;
        if (t == 0) {
            while (*(volatile int*)&g_ready != B_) __nanosleep(32);
            __threadfence();        // acquire: order g_y read after flag
            s_y = __ldcg(&g_y[bc]); // L2 read (bypass possibly-stale L1)
        }
        __syncthreads();
        const float yv = s_y;

        p0.x += yv; p0.y += yv; p0.z += yv; p0.w += yv;
        p1.x += yv; p1.y += yv; p1.z += yv; p1.w += yv;
        p2.x += yv; p2.y += yv; p2.z += yv; p2.w += yv;
        p3.x += yv; p3.y += yv; p3.z += yv; p3.w += yv;

        out4[t]       = p0;
        out4[t + 256] = p1;
        out4[t + 512] = p2;
        out4[t + 768] = p3;
    }

    // ---- self-reset of counters for deterministic graph replay ----
    if (t == 0) {
        __threadfence();
        int d = atomicAdd(&g_done, 1);
        if (d == GRID_ - 1) {       // last CTA in the launch
            g_ready = 0;
            __threadfence();
            g_done = 0;
        }
    }
}

extern "C" void kernel_launch(void* const* d_in, const int* in_sizes, int n_in,
                              void* d_out, int out_size)
{
    // metadata order: img, act, gn_w, gn_b, ln_w, ln_b, qw, qb, kw, kb,
    //                 vw, vb, ow, ob
    const float* img  = (const float*)d_in[0];
    const float* act  = (const float*)d_in[1];
    const float* ln_w = (const float*)d_in[4];
    const float* ln_b = (const float*)d_in[5];
    const float* vw   = (const float*)d_in[10];
    const float* vb   = (const float*)d_in[11];
    const float* ow   = (const float*)d_in[12];
    const float* ob   = (const float*)d_in[13];

    fused_xattn_kernel<<<GRID_, 256>>>(img, act, ln_w, ln_b,
                                       vw, vb, ow, ob, (float*)d_out);
}